// round 2
// baseline (speedup 1.0000x reference)
#include <cuda_runtime.h>
#include <math.h>

// x: (16, 10, 512, 512) f32. out: (16, 8, 512, 512) f32.
// Per pixel: mag = sqrt(x[8]^2 + x[9]^2); k = argmax over x[0..7] (first max);
// out[c] = (c==k) ? mag : 0.
//
// One thread per float4 (4 consecutive pixels). Channel stride = 65536 float4s.
// All accesses 16B coalesced. Streaming cache hints (no reuse anywhere).

#define VPB 65536            // float4 vectors per channel (512*512/4)
#define NBATCH 16
#define TOTAL_VEC (NBATCH * VPB)   // 1,048,576 threads exactly

__global__ __launch_bounds__(256) void histogram_layer_kernel(
    const float4* __restrict__ x, float4* __restrict__ out)
{
    int i = blockIdx.x * blockDim.x + threadIdx.x;  // grid is exact, no guard

    int b = i >> 16;          // i / VPB
    int p = i & (VPB - 1);    // i % VPB

    const float4* in_base = x + (size_t)b * 10 * VPB + p;

    // Front-batched loads: 8 cosines + 2 grads, all streaming (evict-first).
    float4 c[8];
#pragma unroll
    for (int k = 0; k < 8; k++) c[k] = __ldcs(&in_base[(size_t)k * VPB]);
    float4 g0 = __ldcs(&in_base[(size_t)8 * VPB]);
    float4 g1 = __ldcs(&in_base[(size_t)9 * VPB]);

    // Per-lane argmax (strict > keeps lowest index on ties, like jnp.argmax)
    float bx = c[0].x, by = c[0].y, bz = c[0].z, bw = c[0].w;
    int ix = 0, iy = 0, iz = 0, iw = 0;
#pragma unroll
    for (int k = 1; k < 8; k++) {
        if (c[k].x > bx) { bx = c[k].x; ix = k; }
        if (c[k].y > by) { by = c[k].y; iy = k; }
        if (c[k].z > bz) { bz = c[k].z; iz = k; }
        if (c[k].w > bw) { bw = c[k].w; iw = k; }
    }

    float mx = sqrtf(g0.x * g0.x + g1.x * g1.x);
    float my = sqrtf(g0.y * g0.y + g1.y * g1.y);
    float mz = sqrtf(g0.z * g0.z + g1.z * g1.z);
    float mw = sqrtf(g0.w * g0.w + g1.w * g1.w);

    float4* out_base = out + (size_t)b * 8 * VPB + p;
#pragma unroll
    for (int k = 0; k < 8; k++) {
        float4 o;
        o.x = (ix == k) ? mx : 0.0f;
        o.y = (iy == k) ? my : 0.0f;
        o.z = (iz == k) ? mz : 0.0f;
        o.w = (iw == k) ? mw : 0.0f;
        __stcs(&out_base[(size_t)k * VPB], o);
    }
}

extern "C" void kernel_launch(void* const* d_in, const int* in_sizes, int n_in,
                              void* d_out, int out_size)
{
    const float4* x = (const float4*)d_in[0];
    float4* out = (float4*)d_out;
    histogram_layer_kernel<<<TOTAL_VEC / 256, 256>>>(x, out);
}

// round 3
// speedup vs baseline: 1.0208x; 1.0208x over previous
#include <cuda_runtime.h>
#include <math.h>

// x: (16, 10, 512, 512) f32. out: (16, 8, 512, 512) f32.
// Per pixel: mag = sqrt(x[8]^2 + x[9]^2); k = argmax over x[0..7] (first max);
// out[c] = (c==k) ? mag : 0.
//
// One thread per float4 (4 consecutive pixels). Channel stride = 65536 float4s.
// __launch_bounds__(256, 4) allows 64 regs/thread so ptxas can front-batch all
// ten LDG.E.128 before the argmax chain -> MLP_p1 ~ 10 per warp.

#define VPB 65536            // float4 vectors per channel (512*512/4)
#define NBATCH 16
#define TOTAL_VEC (NBATCH * VPB)   // 1,048,576 threads exactly

__global__ __launch_bounds__(256, 4) void histogram_layer_kernel(
    const float4* __restrict__ x, float4* __restrict__ out)
{
    int i = blockIdx.x * blockDim.x + threadIdx.x;  // grid exact, no guard

    int b = i >> 16;          // i / VPB
    int p = i & (VPB - 1);    // i % VPB

    const float4* in_base = x + (size_t)b * 10 * VPB + p;

    // Front-batch ALL ten loads into live registers before any consumption.
    float4 c0 = in_base[(size_t)0 * VPB];
    float4 c1 = in_base[(size_t)1 * VPB];
    float4 c2 = in_base[(size_t)2 * VPB];
    float4 c3 = in_base[(size_t)3 * VPB];
    float4 c4 = in_base[(size_t)4 * VPB];
    float4 c5 = in_base[(size_t)5 * VPB];
    float4 c6 = in_base[(size_t)6 * VPB];
    float4 c7 = in_base[(size_t)7 * VPB];
    float4 g0 = in_base[(size_t)8 * VPB];
    float4 g1 = in_base[(size_t)9 * VPB];

    // Per-lane argmax (strict > keeps lowest index on ties, like jnp.argmax)
    float4 cs[8] = {c0, c1, c2, c3, c4, c5, c6, c7};
    float bx = cs[0].x, by = cs[0].y, bz = cs[0].z, bw = cs[0].w;
    int ix = 0, iy = 0, iz = 0, iw = 0;
#pragma unroll
    for (int k = 1; k < 8; k++) {
        if (cs[k].x > bx) { bx = cs[k].x; ix = k; }
        if (cs[k].y > by) { by = cs[k].y; iy = k; }
        if (cs[k].z > bz) { bz = cs[k].z; iz = k; }
        if (cs[k].w > bw) { bw = cs[k].w; iw = k; }
    }

    float mx = sqrtf(g0.x * g0.x + g1.x * g1.x);
    float my = sqrtf(g0.y * g0.y + g1.y * g1.y);
    float mz = sqrtf(g0.z * g0.z + g1.z * g1.z);
    float mw = sqrtf(g0.w * g0.w + g1.w * g1.w);

    float4* out_base = out + (size_t)b * 8 * VPB + p;
#pragma unroll
    for (int k = 0; k < 8; k++) {
        float4 o;
        o.x = (ix == k) ? mx : 0.0f;
        o.y = (iy == k) ? my : 0.0f;
        o.z = (iz == k) ? mz : 0.0f;
        o.w = (iw == k) ? mw : 0.0f;
        out_base[(size_t)k * VPB] = o;
    }
}

extern "C" void kernel_launch(void* const* d_in, const int* in_sizes, int n_in,
                              void* d_out, int out_size)
{
    const float4* x = (const float4*)d_in[0];
    float4* out = (float4*)d_out;
    histogram_layer_kernel<<<TOTAL_VEC / 256, 256>>>(x, out);
}